// round 10
// baseline (speedup 1.0000x reference)
#include <cuda_runtime.h>
#include <math.h>

#define BB 256
#define VV 16
#define TT 64
#define PP 24
#define FF 8
#define HH 256
#define G4 1024
#define OUTD 4
#define ST 18   // padded float stride for transposed tiles (even -> 8B aligned pairs)

// ---------------- device scratch ----------------
__device__ float g_enc[BB * VV * TT * HH];
__device__ float g_hA[BB * VV * HH];
__device__ float g_hB[BB * VV * HH];
__device__ float g_c [BB * VV * HH];
__device__ float g_prev[BB * VV * FF];
__device__ float g_Whh[VV * HH * G4];      // [v][k][g]
__device__ float g_Wih[VV * FF * G4];      // [v][f][g]
__device__ float g_bg [VV * G4];
__device__ float g_Watt[VV * 2 * HH * HH]; // [v][k(512)][hcol]

typedef unsigned long long u64;

__device__ __forceinline__ u64 pk2(float lo, float hi) {
    u64 r; asm("mov.b64 %0,{%1,%2};" : "=l"(r)
               : "r"(__float_as_uint(lo)), "r"(__float_as_uint(hi)));
    return r;
}
__device__ __forceinline__ u64 dup2(float x) { return pk2(x, x); }
__device__ __forceinline__ float2 upk2(u64 v) {
    unsigned lo, hi; asm("mov.b64 {%0,%1},%2;" : "=r"(lo), "=r"(hi) : "l"(v));
    return make_float2(__uint_as_float(lo), __uint_as_float(hi));
}
__device__ __forceinline__ u64 fma2(u64 a, u64 b, u64 c) {
    u64 d; asm("fma.rn.f32x2 %0,%1,%2,%3;" : "=l"(d) : "l"(a), "l"(b), "l"(c));
    return d;
}
__device__ __forceinline__ u64 mul2(u64 a, u64 b) {
    u64 d; asm("mul.rn.f32x2 %0,%1,%2;" : "=l"(d) : "l"(a), "l"(b));
    return d;
}
__device__ __forceinline__ float sigf(float x) { return 1.0f / (1.0f + __expf(-x)); }

// ---------------- prep: transpose weights to k-major ----------------
__global__ void prep_kernel(const float* __restrict__ Wih,
                            const float* __restrict__ Whh,
                            const float* __restrict__ bih,
                            const float* __restrict__ bhh,
                            const float* __restrict__ Watt) {
    int idx0 = blockIdx.x * blockDim.x + threadIdx.x;
    int stride = gridDim.x * blockDim.x;
    for (int idx = idx0; idx < VV * G4 * HH; idx += stride) {
        int v = idx >> 18; int rem = idx & 262143; int g = rem >> 8; int k = rem & 255;
        g_Whh[(v * HH + k) * G4 + g] = Whh[idx];
    }
    for (int idx = idx0; idx < VV * G4 * FF; idx += stride) {
        int v = idx >> 13; int rem = idx & 8191; int g = rem >> 3; int f = rem & 7;
        g_Wih[(v * FF + f) * G4 + g] = Wih[idx];
    }
    for (int idx = idx0; idx < VV * G4; idx += stride)
        g_bg[idx] = bih[idx] + bhh[idx];
    for (int idx = idx0; idx < VV * HH * 2 * HH; idx += stride) {
        int v = idx >> 17; int rem = idx & 131071; int h = rem >> 9; int k = rem & 511;
        g_Watt[(v * 512 + k) * HH + h] = Watt[idx];
    }
}

// ---------------- packed gate GEMM ----------------
// acc[q][p] holds gate-quadrant q, rows {2p,2p+1}, column tid.
__device__ __forceinline__ void gates_gemm2(const float* __restrict__ xsT,  // [f][ST]
                                            const float* __restrict__ hT,   // [k][ST]
                                            const float* __restrict__ wih,
                                            const float* __restrict__ whh,
                                            const float* __restrict__ bg,
                                            int tid, u64 acc[4][8]) {
#pragma unroll
    for (int q = 0; q < 4; q++) {
        u64 bd = dup2(bg[q * 256 + tid]);
#pragma unroll
        for (int p = 0; p < 8; p++) acc[q][p] = bd;
    }
#pragma unroll
    for (int f = 0; f < 8; f++) {
        u64 d0 = dup2(wih[f * G4 + tid]);
        u64 d1 = dup2(wih[f * G4 + 256 + tid]);
        u64 d2 = dup2(wih[f * G4 + 512 + tid]);
        u64 d3 = dup2(wih[f * G4 + 768 + tid]);
        const u64* xp = (const u64*)(xsT + f * ST);
#pragma unroll
        for (int p = 0; p < 8; p++) {
            u64 x2 = xp[p];
            acc[0][p] = fma2(x2, d0, acc[0][p]);
            acc[1][p] = fma2(x2, d1, acc[1][p]);
            acc[2][p] = fma2(x2, d2, acc[2][p]);
            acc[3][p] = fma2(x2, d3, acc[3][p]);
        }
    }
#pragma unroll 2
    for (int k = 0; k < HH; k++) {
        const float* wr = whh + k * G4 + tid;
        u64 d0 = dup2(wr[0]);
        u64 d1 = dup2(wr[256]);
        u64 d2 = dup2(wr[512]);
        u64 d3 = dup2(wr[768]);
        const u64* hp = (const u64*)(hT + k * ST);
#pragma unroll
        for (int p = 0; p < 8; p++) {
            u64 h2 = hp[p];
            acc[0][p] = fma2(h2, d0, acc[0][p]);
            acc[1][p] = fma2(h2, d1, acc[1][p]);
            acc[2][p] = fma2(h2, d2, acc[2][p]);
            acc[3][p] = fma2(h2, d3, acc[3][p]);
        }
    }
}

// ---------------- encoder ----------------
__global__ __launch_bounds__(256, 2) void encoder_kernel(const float* __restrict__ seq) {
    __shared__ __align__(8) float hT[HH * ST];
    __shared__ __align__(8) float xsT[FF * ST];
    const int tid = threadIdx.x;
    const int v  = blockIdx.x >> 4;
    const int b0 = (blockIdx.x & 15) << 4;
    const float* wih = g_Wih + v * (FF * G4);
    const float* whh = g_Whh + v * (HH * G4);
    const float* bg  = g_bg + v * G4;

    float c_reg[16];
#pragma unroll
    for (int j = 0; j < 16; j++) c_reg[j] = 0.f;
    for (int i = tid; i < HH * ST; i += 256) hT[i] = 0.f;
    __syncthreads();

    for (int t = 0; t < TT; t++) {
        if (tid < 128) {
            int j = tid >> 3, f = tid & 7;
            xsT[f * ST + j] = seq[((b0 + j) * VV + v) * (TT * FF) + t * FF + f];
        }
        __syncthreads();           // hT writes (prev iter) + xsT ready
        u64 acc[4][8];
        gates_gemm2(xsT, hT, wih, whh, bg, tid, acc);
        __syncthreads();           // all hT reads done before rewrite
#pragma unroll
        for (int p = 0; p < 8; p++) {
            float2 gi = upk2(acc[0][p]), gf = upk2(acc[1][p]);
            float2 gg = upk2(acc[2][p]), go = upk2(acc[3][p]);
            {
                int j = 2 * p;
                float c = sigf(gf.x) * c_reg[j] + sigf(gi.x) * tanhf(gg.x);
                float h = sigf(go.x) * tanhf(c);
                c_reg[j] = c;
                hT[tid * ST + j] = h;
                g_enc[(((b0 + j) * VV + v) * TT + t) * HH + tid] = h;
            }
            {
                int j = 2 * p + 1;
                float c = sigf(gf.y) * c_reg[j] + sigf(gi.y) * tanhf(gg.y);
                float h = sigf(go.y) * tanhf(c);
                c_reg[j] = c;
                hT[tid * ST + j] = h;
                g_enc[(((b0 + j) * VV + v) * TT + t) * HH + tid] = h;
            }
        }
    }
    __syncthreads();
#pragma unroll
    for (int j = 0; j < 16; j++) {
        int gi = ((b0 + j) * VV + v) * HH + tid;
        g_hA[gi] = hT[tid * ST + j];
        g_c[gi]  = c_reg[j];
    }
    if (tid < 128) {
        int m = tid >> 3, f = tid & 7;
        g_prev[((b0 + m) * VV + v) * FF + f] =
            seq[((b0 + m) * VV + v) * (TT * FF) + (TT - 1) * FF + f];
    }
}

// ---------------- decoder step ----------------
// dyn smem: hsrc[4096] (reused as h2s) | catT[512*ST] | hattT[256*ST] | psT[8*ST]
// catT[k][j]: feature k in [0,512), LOCAL ROW j in [0,16) (b2 = ci + 16*j).
#define OFF_CATT  4096
#define OFF_HATT  (4096 + 512 * ST)
#define OFF_PST   (4096 + 512 * ST + 256 * ST)
#define DEC_SMEM  ((4096 + 512 * ST + 256 * ST + 8 * ST) * 4)

__global__ __launch_bounds__(256, 2) void decoder_kernel(
    const float* __restrict__ mask, const float* __restrict__ maxv,
    const float* __restrict__ minv, const float* __restrict__ batt,
    const float* __restrict__ wout, const float* __restrict__ bout,
    float* __restrict__ dout, int p) {
    extern __shared__ float sm[];
    float* hsrc  = sm;             // [16][256] (slot-major), later h2s (row-major)
    float* catT  = sm + OFF_CATT;  // [512][ST], row coord = local row j
    float* hattT = sm + OFF_HATT;  // [256][ST]
    float* psT   = sm + OFF_PST;   // [8][ST]
    const int tid = threadIdx.x;
    const int v  = blockIdx.x >> 4;
    const int ci = blockIdx.x & 15;
    const float* h_in  = (p & 1) ? g_hB : g_hA;
    float*       h_out = (p & 1) ? g_hA : g_hB;
    const float* bg = g_bg + v * G4;

    // loads: hsrc (slot s -> row r), c into regs, ps
    for (int i = tid; i < 4096; i += 256) {
        int s = i >> 8, hc = i & 255;
        int r = 2 * ci + 32 * (s >> 1) + (s & 1);
        hsrc[i] = h_in[(r * VV + v) * HH + hc];
    }
    float c_reg[16];
#pragma unroll
    for (int j = 0; j < 16; j++)
        c_reg[j] = g_c[((ci + 16 * j) * VV + v) * HH + tid];
    if (tid < 128) {
        int j = tid >> 3, f = tid & 7;
        int b2 = ci + 16 * j;
        float prev = g_prev[(b2 * VV + v) * FF + f];
        float mx = maxv[b2 * FF + f], mn = minv[b2 * FF + f];
        psT[f * ST + j] = fmaf(prev, mx - mn, mn);
    }
    __syncthreads();

    // attention (online softmax), packed; warp w -> slots 2w,2w+1
    {
        const int w = tid >> 5, lane = tid & 31;
        const int r0 = 2 * ci + 32 * w;
        const float* e0 = g_enc + (size_t)(r0 * VV + v) * (TT * HH);
        const float* e1 = e0 + (size_t)VV * TT * HH;
        const float* mk0 = mask + (r0 * VV + v) * TT;
        const float* mk1 = mk0 + VV * TT;
        const u64* h0p = (const u64*)(hsrc + (2 * w) * HH);
        const u64* h1p = h0p + 128;
        u64 cv0[4] = {0, 0, 0, 0}, cv1[4] = {0, 0, 0, 0};
        float M0 = -1e30f, S0 = 0.f, M1 = -1e30f, S1 = 0.f;
        for (int t = 0; t < TT; t++) {
            u64 e0v[4], e1v[4];
            u64 pd0 = 0, pd1 = 0;
            const u64* er0 = (const u64*)(e0 + t * HH);
            const u64* er1 = (const u64*)(e1 + t * HH);
#pragma unroll
            for (int q = 0; q < 4; q++) {
                e0v[q] = er0[lane + 32 * q];
                pd0 = fma2(e0v[q], h0p[lane + 32 * q], pd0);
            }
#pragma unroll
            for (int q = 0; q < 4; q++) {
                e1v[q] = er1[lane + 32 * q];
                pd1 = fma2(e1v[q], h1p[lane + 32 * q], pd1);
            }
            float2 s0 = upk2(pd0), s1 = upk2(pd1);
            float p0 = s0.x + s0.y, p1 = s1.x + s1.y;
#pragma unroll
            for (int off = 16; off; off >>= 1) {
                p0 += __shfl_xor_sync(0xffffffffu, p0, off);
                p1 += __shfl_xor_sync(0xffffffffu, p1, off);
            }
            p0 *= mk0[t];
            p1 *= mk1[t];
            float nM0 = fmaxf(M0, p0);
            float c0f = __expf(M0 - nM0), w0f = __expf(p0 - nM0);
            S0 = S0 * c0f + w0f; M0 = nM0;
            u64 cd0 = dup2(c0f), wd0 = dup2(w0f);
#pragma unroll
            for (int q = 0; q < 4; q++) cv0[q] = fma2(wd0, e0v[q], mul2(cv0[q], cd0));
            float nM1 = fmaxf(M1, p1);
            float c1f = __expf(M1 - nM1), w1f = __expf(p1 - nM1);
            S1 = S1 * c1f + w1f; M1 = nM1;
            u64 cd1 = dup2(c1f), wd1 = dup2(w1f);
#pragma unroll
            for (int q = 0; q < 4; q++) cv1[q] = fma2(wd1, e1v[q], mul2(cv1[q], cd1));
        }
        // FIXED layout: local row j=w holds [cv(r0) | cv(r1)] along the
        // 512-feature axis: cv0 -> features col, cv1 -> features 256+col.
        float i0 = 1.f / S0, i1 = 1.f / S1;
#pragma unroll
        for (int q = 0; q < 4; q++) {
            float2 a0 = upk2(cv0[q]), a1 = upk2(cv1[q]);
            int col = 2 * (lane + 32 * q);
            catT[col * ST + w]             = a0.x * i0;
            catT[(col + 1) * ST + w]       = a0.y * i0;
            catT[(256 + col) * ST + w]     = a1.x * i1;
            catT[(256 + col + 1) * ST + w] = a1.y * i1;
        }
    }
    // FIXED high half: local row j = 8 + (s>>1) holds
    // [hsrc slot 2(s>>1) | hsrc slot 2(s>>1)+1]; slot s contributes
    // features (s&1)*256 + hc.
    for (int i = tid; i < 4096; i += 256) {
        int s = i >> 8, hc = i & 255;
        catT[(((s & 1) << 8) + hc) * ST + 8 + (s >> 1)] = hsrc[i];
    }
    __syncthreads();

    // h_att = tanh(cat @ Watt^T + b_att), thread owns column tid
    {
        u64 a[8];
        u64 bd = dup2(batt[v * HH + tid]);
#pragma unroll
        for (int pq = 0; pq < 8; pq++) a[pq] = bd;
        const float* wa = g_Watt + v * (512 * HH) + tid;
#pragma unroll 2
        for (int k = 0; k < 512; k++) {
            u64 wd = dup2(wa[k * HH]);
            const u64* cp = (const u64*)(catT + k * ST);
#pragma unroll
            for (int pq = 0; pq < 8; pq++) a[pq] = fma2(cp[pq], wd, a[pq]);
        }
#pragma unroll
        for (int pq = 0; pq < 8; pq++) {
            float2 t2 = upk2(a[pq]);
            hattT[tid * ST + 2 * pq]     = tanhf(t2.x);
            hattT[tid * ST + 2 * pq + 1] = tanhf(t2.y);
        }
    }
    __syncthreads();

    // LSTM gates + elementwise (local accs, no gates smem)
    {
        u64 acc[4][8];
        gates_gemm2(psT, hattT, g_Wih + v * (FF * G4), g_Whh + v * (HH * G4),
                    bg, tid, acc);
        float* h2s = hsrc;  // reuse
#pragma unroll
        for (int pq = 0; pq < 8; pq++) {
            float2 gi = upk2(acc[0][pq]), gf = upk2(acc[1][pq]);
            float2 gg = upk2(acc[2][pq]), go = upk2(acc[3][pq]);
            {
                int j = 2 * pq;
                float c = sigf(gf.x) * c_reg[j] + sigf(gi.x) * tanhf(gg.x);
                float h = sigf(go.x) * tanhf(c);
                int b2 = ci + 16 * j;
                g_c[(b2 * VV + v) * HH + tid] = c;
                h_out[(b2 * VV + v) * HH + tid] = h;
                h2s[j * 256 + tid] = h;
            }
            {
                int j = 2 * pq + 1;
                float c = sigf(gf.y) * c_reg[j] + sigf(gi.y) * tanhf(gg.y);
                float h = sigf(go.y) * tanhf(c);
                int b2 = ci + 16 * j;
                g_c[(b2 * VV + v) * HH + tid] = c;
                h_out[(b2 * VV + v) * HH + tid] = h;
                h2s[j * 256 + tid] = h;
            }
        }
    }
    __syncthreads();

    // output projection (packed)
    if (tid < 128) {
        int j = tid >> 3, f = tid & 7;
        int b2 = ci + 16 * j;
        const u64* wr = (const u64*)(wout + f * HH);
        const u64* hr = (const u64*)(hsrc + j * 256);
        u64 av = 0;
#pragma unroll 4
        for (int pi = 0; pi < 128; pi++) av = fma2(wr[pi], hr[pi], av);
        float2 s = upk2(av);
        float o = fmaxf(s.x + s.y + bout[f], 0.f);
        g_prev[(b2 * VV + v) * FF + f] = o;
        if (f < OUTD)
            dout[((b2 * VV + v) * PP + p) * OUTD + f] = fminf(o, 1.f);
    }
}

// ---------------- launch ----------------
extern "C" void kernel_launch(void* const* d_in, const int* in_sizes, int n_in,
                              void* d_out, int out_size) {
    const float* seq  = (const float*)d_in[0];
    const float* mask = (const float*)d_in[4];
    const float* maxv = (const float*)d_in[5];
    const float* minv = (const float*)d_in[6];
    const float* Wih  = (const float*)d_in[7];
    const float* Whh  = (const float*)d_in[8];
    const float* bih  = (const float*)d_in[9];
    const float* bhh  = (const float*)d_in[10];
    const float* Watt = (const float*)d_in[11];
    const float* batt = (const float*)d_in[12];
    const float* Wout = (const float*)d_in[13];
    const float* bout = (const float*)d_in[14];
    float* out = (float*)d_out;

    cudaFuncSetAttribute(decoder_kernel, cudaFuncAttributeMaxDynamicSharedMemorySize, DEC_SMEM);

    prep_kernel<<<4096, 256>>>(Wih, Whh, bih, bhh, Watt);
    encoder_kernel<<<VV * 16, 256>>>(seq);
    for (int p = 0; p < PP; p++) {
        decoder_kernel<<<VV * 16, 256, DEC_SMEM>>>(mask, maxv, minv, batt, Wout, bout, out, p);
    }
}